// round 12
// baseline (speedup 1.0000x reference)
#include <cuda_runtime.h>
#include <math.h>

// Problem dims (fixed by the reference)
#define NB 2048   // batch
#define NI 256    // inner / contraction dim j
#define NO 256    // output dim i

typedef unsigned long long ull;

// Global trig tables, pair-interleaved j-major:
//   float index = j2*R*2 + r*2 + (j&1),  R = NB (x-side) or NO (o-side)
__device__ __align__(16) float g_cx2[NI * NB];  // cos(phi0 + x)
__device__ __align__(16) float g_sx2[NI * NB];  // sin(phi0 + x)
__device__ __align__(16) float g_nc2[NI * NO];  // -2*rho*cos(off)
__device__ __align__(16) float g_so2[NI * NO];  //  2*rho*sin(off)

// ---------------- prep: both tables in one launch ----------------
__global__ void prep_all(const float* __restrict__ x, const float* __restrict__ off,
                         float phi0, float two_rho) {
    __shared__ float tile[32][33];
    const int blk = blockIdx.x;
    const float* src;
    float *dc, *ds;
    int R, r0, j0;
    float addp, mc, ms;
    if (blk < 512) {               // x-table: 64 b-tiles x 8 j-tiles
        r0 = (blk >> 3) * 32; j0 = (blk & 7) * 32;
        src = x;  dc = g_cx2; ds = g_sx2; R = NB;
        addp = phi0; mc = 1.0f; ms = 1.0f;
    } else {                       // off-table: 8 i-tiles x 8 j-tiles
        int q = blk - 512;
        r0 = (q >> 3) * 32; j0 = (q & 7) * 32;
        src = off; dc = g_nc2; ds = g_so2; R = NO;
        addp = 0.0f; mc = -two_rho; ms = two_rho;
    }
    const int lane = threadIdx.x & 31;
    const int w8   = threadIdx.x >> 5;
    #pragma unroll
    for (int rr = 0; rr < 4; ++rr)
        tile[w8 + rr * 8][lane] = src[(r0 + w8 + rr * 8) * NI + j0 + lane];
    __syncthreads();
    #pragma unroll
    for (int k = 0; k < 4; ++k) {
        int jj = w8 + k * 8, ri = lane;
        float s, c;
        __sincosf(addp + tile[ri][jj], &s, &c);
        int idx = (((j0 + jj) >> 1) * R + (r0 + ri)) * 2 + (jj & 1);
        dc[idx] = mc * c;
        ds[idx] = ms * s;
    }
}

// ---------------- packed f32x2 + misc helpers ----------------
__device__ __forceinline__ ull ffma2(ull a, ull b, ull c) {
    ull d;
    asm("fma.rn.f32x2 %0, %1, %2, %3;" : "=l"(d) : "l"(a), "l"(b), "l"(c));
    return d;
}
__device__ __forceinline__ ull fadd2(ull a, ull b) {
    ull d;
    asm("add.rn.f32x2 %0, %1, %2;" : "=l"(d) : "l"(a), "l"(b));
    return d;
}
__device__ __forceinline__ ull fmul2(ull a, ull b) {
    ull d;
    asm("mul.rn.f32x2 %0, %1, %2;" : "=l"(d) : "l"(a), "l"(b));
    return d;
}
__device__ __forceinline__ float2 u2f(ull v) {
    float2 r;
    asm("mov.b64 {%0, %1}, %2;" : "=f"(r.x), "=f"(r.y) : "l"(v));
    return r;
}
__device__ __forceinline__ float frcp(float x) {
    float r;
    asm("rcp.approx.f32 %0, %1;" : "=f"(r) : "f"(x));
    return r;
}

// 4 j-terms fused: sum 1/d = (S.x*P.y + S.y*P.x) * rcp(P.x*P.y), S=D+E, P=D*E.
#define QCELL(acc, cA, sA, cB, sB, nA, oA, nB, oB)                     \
    do {                                                               \
        ull D_ = ffma2((cA), (nA), ffma2((sA), (oA), Q2));             \
        ull E_ = ffma2((cB), (nB), ffma2((sB), (oB), Q2));             \
        float2 S_ = u2f(fadd2(D_, E_));                                \
        float2 P_ = u2f(fmul2(D_, E_));                                \
        (acc) = fmaf(fmaf(S_.x, P_.y, S_.y * P_.x),                    \
                     frcp(P_.x * P_.y), (acc));                        \
    } while (0)

// CTA: 128 threads, tile 16(b) x 32(i), micro-tile 2b x 2i.
// grid (128, 8) = 1024 CTAs -> ~7 CTAs/SM, wave imbalance ~1.01.
// NO shared memory, NO barriers: operands read straight from the L2-resident
// trig tables via LDG.128 with unroll-8 front-batched loads (deep MLP).
__global__ __launch_bounds__(128) void photonic_main(float* __restrict__ out,
                                                     ull Q2, float negK) {
    const int t  = threadIdx.x;
    const int tx = t & 7;                    // 8 groups along b (2 b each)
    const int ty = t >> 3;                   // 16 groups along i (2 i each)
    const int b_blk = blockIdx.x * 16;
    const int i_blk = blockIdx.y * 32;

    // This thread's operand columns (16B each) within every j-pair row.
    const float* cxp = g_cx2 + b_blk * 2 + tx * 4;   // + j2 * 2*NB
    const float* sxp = g_sx2 + b_blk * 2 + tx * 4;
    const float* ncp = g_nc2 + i_blk * 2 + ty * 4;   // + j2 * 2*NO
    const float* sop = g_so2 + i_blk * 2 + ty * 4;

    float a00 = 0.f, a01 = 0.f, a10 = 0.f, a11 = 0.f;

    #pragma unroll 8
    for (int j2 = 0; j2 < NI / 2; j2 += 2) {   // 4 j per iteration
        const ulonglong2 cxA = *(const ulonglong2*)(cxp + (j2    ) * (2 * NB));
        const ulonglong2 cxB = *(const ulonglong2*)(cxp + (j2 + 1) * (2 * NB));
        const ulonglong2 sxA = *(const ulonglong2*)(sxp + (j2    ) * (2 * NB));
        const ulonglong2 sxB = *(const ulonglong2*)(sxp + (j2 + 1) * (2 * NB));
        const ulonglong2 nA  = *(const ulonglong2*)(ncp + (j2    ) * (2 * NO));
        const ulonglong2 nB  = *(const ulonglong2*)(ncp + (j2 + 1) * (2 * NO));
        const ulonglong2 oA  = *(const ulonglong2*)(sop + (j2    ) * (2 * NO));
        const ulonglong2 oB  = *(const ulonglong2*)(sop + (j2 + 1) * (2 * NO));

        // (b0, i0) / (b0, i1)
        QCELL(a00, cxA.x, sxA.x, cxB.x, sxB.x, nA.x, oA.x, nB.x, oB.x);
        QCELL(a01, cxA.x, sxA.x, cxB.x, sxB.x, nA.y, oA.y, nB.y, oB.y);
        // (b1, i0) / (b1, i1)
        QCELL(a10, cxA.y, sxA.y, cxB.y, sxB.y, nA.x, oA.x, nB.x, oB.x);
        QCELL(a11, cxA.y, sxA.y, cxB.y, sxB.y, nA.y, oA.y, nB.y, oB.y);
    }

    const int b0 = b_blk + tx * 2;
    const int i0 = i_blk + ty * 2;
    float2 r0, r1;
    r0.x = fmaf(negK, a00, (float)NI);
    r0.y = fmaf(negK, a01, (float)NI);
    r1.x = fmaf(negK, a10, (float)NI);
    r1.y = fmaf(negK, a11, (float)NI);
    *(float2*)(out + (b0 + 0) * NO + i0) = r0;
    *(float2*)(out + (b0 + 1) * NO + i0) = r1;
}

extern "C" void kernel_launch(void* const* d_in, const int* in_sizes, int n_in,
                              void* d_out, int out_size) {
    const float* x   = (const float*)d_in[0];   // input_matrix [2048, 256]
    const float* off = (const float*)d_in[1];   // phase_offset [256, 256]
    float* out = (float*)d_out;                 // [2048, 256]

    // Physics constants
    const double PI     = 3.14159265358979323846;
    const double RADIUS = 5e-6;
    const double KAPPA  = 0.1;
    const double N_EFF  = 3.48;
    const double LAMBDA = 1.55e-6;
    const double LOSS_A = 0.99;

    const double t   = sqrt(1.0 - KAPPA);
    const double a   = LOSS_A;
    const double rho = a * t;
    const double phi0 = fmod(2.0 * PI * N_EFF * (2.0 * PI * RADIUS) / LAMBDA, 2.0 * PI);

    const float Qc      = (float)(1.0 + rho * rho);
    const float two_rho = (float)(2.0 * rho);
    const float negK    = (float)(-(1.0 - t * t) * (1.0 - a * a));

    unsigned int qbits;
    memcpy(&qbits, &Qc, 4);
    const ull Q2 = ((ull)qbits << 32) | qbits;   // packed (Qc, Qc)

    prep_all<<<576, 256>>>(x, off, (float)phi0, two_rho);

    dim3 grid(NB / 16, NO / 32);   // (128, 8) = 1024 CTAs
    photonic_main<<<grid, 128>>>(out, Q2, negK);
}

// round 13
// speedup vs baseline: 1.4221x; 1.4221x over previous
#include <cuda_runtime.h>
#include <math.h>

// Problem dims (fixed by the reference)
#define NB 2048   // batch
#define NI 256    // inner / contraction dim j
#define NO 256    // output dim i

#define J_CH 32                    // j per smem stage
#define NCHUNK (NI / J_CH)         // 8
#define ROWS_CH (J_CH / 2)         // 16 j-pair rows per chunk
// per-buffer float offsets: cx[512] sx[512] nc[1024] so[1024]
#define OFF_SX 512
#define OFF_NC 1024
#define OFF_SO 2048
#define BUF_FLOATS 3072            // 12 KB per buffer
#define BUF_BYTES  12288

typedef unsigned long long ull;

// Global trig tables, pair-interleaved j-major:
//   float index = (j2*R + r)*2 + (j&1),  R = NB (x-side) or NO (o-side)
__device__ __align__(16) float g_cx2[NI * NB];  // cos(phi0 + x)
__device__ __align__(16) float g_sx2[NI * NB];  // sin(phi0 + x)
__device__ __align__(16) float g_nc2[NI * NO];  // -2*rho*cos(off)
__device__ __align__(16) float g_so2[NI * NO];  //  2*rho*sin(off)

// ---------------- prep: both tables in one launch ----------------
__global__ void prep_all(const float* __restrict__ x, const float* __restrict__ off,
                         float phi0, float two_rho) {
    __shared__ float tile[32][33];
    const int blk = blockIdx.x;
    const float* src;
    float *dc, *ds;
    int R, r0, j0;
    float addp, mc, ms;
    if (blk < 512) {               // x-table: 64 b-tiles x 8 j-tiles
        r0 = (blk >> 3) * 32; j0 = (blk & 7) * 32;
        src = x;  dc = g_cx2; ds = g_sx2; R = NB;
        addp = phi0; mc = 1.0f; ms = 1.0f;
    } else {                       // off-table: 8 i-tiles x 8 j-tiles
        int q = blk - 512;
        r0 = (q >> 3) * 32; j0 = (q & 7) * 32;
        src = off; dc = g_nc2; ds = g_so2; R = NO;
        addp = 0.0f; mc = -two_rho; ms = two_rho;
    }
    const int lane = threadIdx.x & 31;
    const int w8   = threadIdx.x >> 5;
    #pragma unroll
    for (int rr = 0; rr < 4; ++rr)
        tile[w8 + rr * 8][lane] = src[(r0 + w8 + rr * 8) * NI + j0 + lane];
    __syncthreads();
    #pragma unroll
    for (int k = 0; k < 4; ++k) {
        int jj = w8 + k * 8, ri = lane;
        float s, c;
        __sincosf(addp + tile[ri][jj], &s, &c);
        int idx = (((j0 + jj) >> 1) * R + (r0 + ri)) * 2 + (jj & 1);
        dc[idx] = mc * c;
        ds[idx] = ms * s;
    }
}

// ---------------- packed f32x2 + misc helpers ----------------
__device__ __forceinline__ ull ffma2(ull a, ull b, ull c) {
    ull d;
    asm("fma.rn.f32x2 %0, %1, %2, %3;" : "=l"(d) : "l"(a), "l"(b), "l"(c));
    return d;
}
__device__ __forceinline__ ull fadd2(ull a, ull b) {
    ull d;
    asm("add.rn.f32x2 %0, %1, %2;" : "=l"(d) : "l"(a), "l"(b));
    return d;
}
__device__ __forceinline__ ull fmul2(ull a, ull b) {
    ull d;
    asm("mul.rn.f32x2 %0, %1, %2;" : "=l"(d) : "l"(a), "l"(b));
    return d;
}
__device__ __forceinline__ float2 u2f(ull v) {
    float2 r;
    asm("mov.b64 {%0, %1}, %2;" : "=f"(r.x), "=f"(r.y) : "l"(v));
    return r;
}
__device__ __forceinline__ float frcp(float x) {
    float r;
    asm("rcp.approx.f32 %0, %1;" : "=f"(r) : "f"(x));
    return r;
}
__device__ __forceinline__ void cp16(unsigned dst, const void* src) {
    asm volatile("cp.async.ca.shared.global [%0], [%1], 16;\n" :: "r"(dst), "l"(src));
}

// 4 j-terms fused: sum 1/d = (S.x*P.y + S.y*P.x) * rcp(P.x*P.y), S=D+E, P=D*E.
#define QCELL(acc, cA, sA, cB, sB, nA, oA, nB, oB)                     \
    do {                                                               \
        ull D_ = ffma2((cA), (nA), ffma2((sA), (oA), Q2));             \
        ull E_ = ffma2((cB), (nB), ffma2((sB), (oB), Q2));             \
        float2 S_ = u2f(fadd2(D_, E_));                                \
        float2 P_ = u2f(fmul2(D_, E_));                                \
        (acc) = fmaf(fmaf(S_.x, P_.y, S_.y * P_.x),                    \
                     frcp(P_.x * P_.y), (acc));                        \
    } while (0)

// CTA: 64 threads, tile 16(b) x 32(i), micro-tile 2b x 4i (8 accumulators).
// grid (128, 8) = 1024 CTAs -> ~7 CTAs/SM, wave imbalance ~1.01, 2048 warps.
// Each cx LDS.128 feeds 4 i-cells: wavefronts/elem halved vs the 2bx2i shape.
__global__ __launch_bounds__(64, 7) void photonic_main(float* __restrict__ out,
                                                       ull Q2, float negK) {
    extern __shared__ __align__(16) float sbuf[];   // 2 * 12 KB

    const int t  = threadIdx.x;              // 0..63
    const int tx = t & 7;                    // 8 groups along b (2 b each)
    const int ty = t >> 3;                   // 8 groups along i (4 i each)
    const int b_blk = blockIdx.x * 16;
    const int i_blk = blockIdx.y * 32;

    const unsigned sb = (unsigned)__cvta_generic_to_shared(sbuf);

    // fill coords: cx/sx have 128 16B-chunks (threads t, t+64);
    // nc/so have 256 chunks (threads t, t+64, t+128, t+192).
    const float* pxc = g_cx2 + ((t >> 3) * NB + b_blk) * 2 + (t & 7) * 4;
    const float* pxs = g_sx2 + ((t >> 3) * NB + b_blk) * 2 + (t & 7) * 4;
    const float* pnc = g_nc2 + ((t >> 4) * NO + i_blk) * 2 + (t & 15) * 4;
    const float* pso = g_so2 + ((t >> 4) * NO + i_blk) * 2 + (t & 15) * 4;
    const int xrow8 = 8 * NB * 2;            // 8 j-pair rows, x-side
    const int orow4 = 4 * NO * 2;            // 4 j-pair rows, o-side
    const int xstep = ROWS_CH * NB * 2;      // floats per chunk, x-side
    const int ostep = ROWS_CH * NO * 2;      // floats per chunk, o-side

    auto issue = [&](int c, int p) {
        unsigned base = sb + (unsigned)(p * BUF_BYTES);
        cp16(base + (unsigned)(t * 16),                      pxc + c * xstep);
        cp16(base + (unsigned)((t + 64) * 16),               pxc + c * xstep + xrow8);
        cp16(base + (unsigned)(OFF_SX * 4 + t * 16),         pxs + c * xstep);
        cp16(base + (unsigned)(OFF_SX * 4 + (t + 64) * 16),  pxs + c * xstep + xrow8);
        #pragma unroll
        for (int k = 0; k < 4; ++k) {
            cp16(base + (unsigned)(OFF_NC * 4 + (t + 64 * k) * 16),
                 pnc + c * ostep + k * orow4);
            cp16(base + (unsigned)(OFF_SO * 4 + (t + 64 * k) * 16),
                 pso + c * ostep + k * orow4);
        }
        asm volatile("cp.async.commit_group;\n" ::);
    };

    float a00 = 0.f, a01 = 0.f, a02 = 0.f, a03 = 0.f;
    float a10 = 0.f, a11 = 0.f, a12 = 0.f, a13 = 0.f;

    issue(0, 0);
    issue(1, 1);

    #pragma unroll 1
    for (int c = 0; c < NCHUNK; ++c) {
        if (c < NCHUNK - 1) asm volatile("cp.async.wait_group 1;\n" ::);
        else                asm volatile("cp.async.wait_group 0;\n" ::);
        __syncthreads();

        const int p = c & 1;
        const float* buf = sbuf + p * BUF_FLOATS;
        const float* cxb = buf +          tx * 4;   // 2 b's (row stride 32)
        const float* sxb = buf + OFF_SX + tx * 4;
        const float* ncb = buf + OFF_NC + ty * 8;   // 4 i's (row stride 64)
        const float* sob = buf + OFF_SO + ty * 8;

        #pragma unroll
        for (int jp = 0; jp < ROWS_CH; jp += 2) {   // 4 j per iter, imm offsets
            const ulonglong2 cxA = *(const ulonglong2*)(cxb + (jp    ) * 32);
            const ulonglong2 cxB = *(const ulonglong2*)(cxb + (jp + 1) * 32);
            const ulonglong2 sxA = *(const ulonglong2*)(sxb + (jp    ) * 32);
            const ulonglong2 sxB = *(const ulonglong2*)(sxb + (jp + 1) * 32);
            const ulonglong2 nA0 = *(const ulonglong2*)(ncb + (jp    ) * 64);
            const ulonglong2 nA1 = *(const ulonglong2*)(ncb + (jp    ) * 64 + 4);
            const ulonglong2 nB0 = *(const ulonglong2*)(ncb + (jp + 1) * 64);
            const ulonglong2 nB1 = *(const ulonglong2*)(ncb + (jp + 1) * 64 + 4);
            const ulonglong2 oA0 = *(const ulonglong2*)(sob + (jp    ) * 64);
            const ulonglong2 oA1 = *(const ulonglong2*)(sob + (jp    ) * 64 + 4);
            const ulonglong2 oB0 = *(const ulonglong2*)(sob + (jp + 1) * 64);
            const ulonglong2 oB1 = *(const ulonglong2*)(sob + (jp + 1) * 64 + 4);

            // b0 row: i0..i3
            QCELL(a00, cxA.x, sxA.x, cxB.x, sxB.x, nA0.x, oA0.x, nB0.x, oB0.x);
            QCELL(a01, cxA.x, sxA.x, cxB.x, sxB.x, nA0.y, oA0.y, nB0.y, oB0.y);
            QCELL(a02, cxA.x, sxA.x, cxB.x, sxB.x, nA1.x, oA1.x, nB1.x, oB1.x);
            QCELL(a03, cxA.x, sxA.x, cxB.x, sxB.x, nA1.y, oA1.y, nB1.y, oB1.y);
            // b0+1 row: i0..i3
            QCELL(a10, cxA.y, sxA.y, cxB.y, sxB.y, nA0.x, oA0.x, nB0.x, oB0.x);
            QCELL(a11, cxA.y, sxA.y, cxB.y, sxB.y, nA0.y, oA0.y, nB0.y, oB0.y);
            QCELL(a12, cxA.y, sxA.y, cxB.y, sxB.y, nA1.x, oA1.x, nB1.x, oB1.x);
            QCELL(a13, cxA.y, sxA.y, cxB.y, sxB.y, nA1.y, oA1.y, nB1.y, oB1.y);
        }
        __syncthreads();   // all reads of buffer p done
        if (c + 2 < NCHUNK) issue(c + 2, p);
    }

    const int b0 = b_blk + tx * 2;
    const int i0 = i_blk + ty * 4;
    float4 r0, r1;
    r0.x = fmaf(negK, a00, (float)NI);
    r0.y = fmaf(negK, a01, (float)NI);
    r0.z = fmaf(negK, a02, (float)NI);
    r0.w = fmaf(negK, a03, (float)NI);
    r1.x = fmaf(negK, a10, (float)NI);
    r1.y = fmaf(negK, a11, (float)NI);
    r1.z = fmaf(negK, a12, (float)NI);
    r1.w = fmaf(negK, a13, (float)NI);
    *(float4*)(out + (b0 + 0) * NO + i0) = r0;
    *(float4*)(out + (b0 + 1) * NO + i0) = r1;
}

extern "C" void kernel_launch(void* const* d_in, const int* in_sizes, int n_in,
                              void* d_out, int out_size) {
    const float* x   = (const float*)d_in[0];   // input_matrix [2048, 256]
    const float* off = (const float*)d_in[1];   // phase_offset [256, 256]
    float* out = (float*)d_out;                 // [2048, 256]

    // Physics constants
    const double PI     = 3.14159265358979323846;
    const double RADIUS = 5e-6;
    const double KAPPA  = 0.1;
    const double N_EFF  = 3.48;
    const double LAMBDA = 1.55e-6;
    const double LOSS_A = 0.99;

    const double t   = sqrt(1.0 - KAPPA);
    const double a   = LOSS_A;
    const double rho = a * t;
    const double phi0 = fmod(2.0 * PI * N_EFF * (2.0 * PI * RADIUS) / LAMBDA, 2.0 * PI);

    const float Qc      = (float)(1.0 + rho * rho);
    const float two_rho = (float)(2.0 * rho);
    const float negK    = (float)(-(1.0 - t * t) * (1.0 - a * a));

    unsigned int qbits;
    memcpy(&qbits, &Qc, 4);
    const ull Q2 = ((ull)qbits << 32) | qbits;   // packed (Qc, Qc)

    prep_all<<<576, 256>>>(x, off, (float)phi0, two_rho);

    const int smem_bytes = 2 * BUF_BYTES;   // 24 KB
    cudaFuncSetAttribute(photonic_main,
                         cudaFuncAttributeMaxDynamicSharedMemorySize, smem_bytes);
    dim3 grid(NB / 16, NO / 32);   // (128, 8) = 1024 CTAs
    photonic_main<<<grid, 64, smem_bytes>>>(out, Q2, negK);
}

// round 14
// speedup vs baseline: 1.4911x; 1.0485x over previous
#include <cuda_runtime.h>
#include <math.h>

// Problem dims (fixed by the reference)
#define NB 2048   // batch
#define NI 256    // inner / contraction dim j
#define NO 256    // output dim i

#define J_CH 32                    // j per smem stage
#define NCHUNK (NI / J_CH)         // 8
#define ROWS_CH (J_CH / 2)         // 16 j-pair rows per chunk
// per-buffer float offsets: cx[1024] sx[1024] nc[512] so[512]
#define OFF_SX 1024
#define OFF_NC 2048
#define OFF_SO 2560
#define BUF_FLOATS 3072            // 12 KB per buffer
#define BUF_BYTES  12288

typedef unsigned long long ull;

// Global trig tables, pair-interleaved j-major:
//   float index = (j2*R + r)*2 + (j&1),  R = NB (x-side) or NO (o-side)
__device__ __align__(16) float g_cx2[NI * NB];  // cos(phi0 + x)
__device__ __align__(16) float g_sx2[NI * NB];  // sin(phi0 + x)
__device__ __align__(16) float g_nc2[NI * NO];  // -2*rho*cos(off)
__device__ __align__(16) float g_so2[NI * NO];  //  2*rho*sin(off)

// ---------------- prep: both tables, coalesced float2 writes ----------------
// Block tile: 32 rows x 32 j. Phase 1: coalesced read + smem transpose.
// Phase 2: each thread owns 2 (j-pair, row) cells -> 4 sincos, writes
// float2 per table per cell; warp stores are 256B contiguous.
__global__ void prep_all(const float* __restrict__ x, const float* __restrict__ off,
                         float phi0, float two_rho) {
    __shared__ float tile[32][33];
    const int blk = blockIdx.x;
    const float* src;
    float *dc, *ds;
    int R, r0, j0;
    float addp, mc, ms;
    if (blk < 512) {               // x-table: 64 b-tiles x 8 j-tiles
        r0 = (blk >> 3) * 32; j0 = (blk & 7) * 32;
        src = x;  dc = g_cx2; ds = g_sx2; R = NB;
        addp = phi0; mc = 1.0f; ms = 1.0f;
    } else {                       // off-table: 8 i-tiles x 8 j-tiles
        int q = blk - 512;
        r0 = (q >> 3) * 32; j0 = (q & 7) * 32;
        src = off; dc = g_nc2; ds = g_so2; R = NO;
        addp = 0.0f; mc = -two_rho; ms = two_rho;
    }
    const int lane = threadIdx.x & 31;
    const int w8   = threadIdx.x >> 5;   // 0..7
    // Phase 1: coalesced read (warp reads one 128B row of the tile)
    #pragma unroll
    for (int rr = 0; rr < 4; ++rr)
        tile[w8 + rr * 8][lane] = src[(r0 + w8 + rr * 8) * NI + j0 + lane];
    __syncthreads();
    // Phase 2: thread -> (ri = lane, jp in {w8, w8+8}); float2 writes
    #pragma unroll
    for (int k = 0; k < 2; ++k) {
        const int jp = w8 + k * 8;       // local j-pair 0..15
        const int ri = lane;
        float s0, c0, s1, c1;
        __sincosf(addp + tile[ri][2 * jp    ], &s0, &c0);
        __sincosf(addp + tile[ri][2 * jp + 1], &s1, &c1);
        const int cell = ((j0 >> 1) + jp) * R + (r0 + ri);
        *(float2*)(dc + cell * 2) = make_float2(mc * c0, mc * c1);
        *(float2*)(ds + cell * 2) = make_float2(ms * s0, ms * s1);
    }
}

// ---------------- packed f32x2 + misc helpers ----------------
__device__ __forceinline__ ull ffma2(ull a, ull b, ull c) {
    ull d;
    asm("fma.rn.f32x2 %0, %1, %2, %3;" : "=l"(d) : "l"(a), "l"(b), "l"(c));
    return d;
}
__device__ __forceinline__ ull fadd2(ull a, ull b) {
    ull d;
    asm("add.rn.f32x2 %0, %1, %2;" : "=l"(d) : "l"(a), "l"(b));
    return d;
}
__device__ __forceinline__ ull fmul2(ull a, ull b) {
    ull d;
    asm("mul.rn.f32x2 %0, %1, %2;" : "=l"(d) : "l"(a), "l"(b));
    return d;
}
__device__ __forceinline__ float2 u2f(ull v) {
    float2 r;
    asm("mov.b64 {%0, %1}, %2;" : "=f"(r.x), "=f"(r.y) : "l"(v));
    return r;
}
__device__ __forceinline__ float frcp(float x) {
    float r;
    asm("rcp.approx.f32 %0, %1;" : "=f"(r) : "f"(x));
    return r;
}
__device__ __forceinline__ void cp16(unsigned dst, const void* src) {
    asm volatile("cp.async.ca.shared.global [%0], [%1], 16;\n" :: "r"(dst), "l"(src));
}

// 4 j-terms fused: sum 1/d = (S.x*P.y + S.y*P.x) * rcp(P.x*P.y), S=D+E, P=D*E.
#define QCELL(acc, cA, sA, cB, sB, nA, oA, nB, oB)                     \
    do {                                                               \
        ull D_ = ffma2((cA), (nA), ffma2((sA), (oA), Q2));             \
        ull E_ = ffma2((cB), (nB), ffma2((sB), (oB), Q2));             \
        float2 S_ = u2f(fadd2(D_, E_));                                \
        float2 P_ = u2f(fmul2(D_, E_));                                \
        (acc) = fmaf(fmaf(S_.x, P_.y, S_.y * P_.x),                    \
                     frcp(P_.x * P_.y), (acc));                        \
    } while (0)

// CTA: 128 threads, tile 32(b) x 16(i), micro-tile 2b x 2i.  (R10 config)
// grid (64, 16) = 1024 CTAs -> ~7 CTAs/SM, wave imbalance ~1.01.
__global__ __launch_bounds__(128, 7) void photonic_main(float* __restrict__ out,
                                                        ull Q2, float negK) {
    extern __shared__ __align__(16) float sbuf[];   // 2 * 12 KB

    const int t  = threadIdx.x;
    const int tx = t & 15;                   // 16 groups along b (2 b each)
    const int ty = t >> 4;                   // 8 groups along i (2 i each)
    const int b_blk = blockIdx.x * 32;
    const int i_blk = blockIdx.y * 16;

    const unsigned sb = (unsigned)__cvta_generic_to_shared(sbuf);

    // fill coords: x-tables have 256 16B-chunks each -> threads t and t+128;
    // o-tables have 128 16B-chunks -> thread t.
    const int xr0 = t >> 4,         xs0 = t & 15;
    const int xr1 = (t + 128) >> 4, xs1 = t & 15;
    const int orow = t >> 3,        oseg = t & 7;

    const float* pxc0 = g_cx2 + (xr0 * NB + b_blk) * 2 + xs0 * 4;
    const float* pxc1 = g_cx2 + (xr1 * NB + b_blk) * 2 + xs1 * 4;
    const float* pxs0 = g_sx2 + (xr0 * NB + b_blk) * 2 + xs0 * 4;
    const float* pxs1 = g_sx2 + (xr1 * NB + b_blk) * 2 + xs1 * 4;
    const float* poc  = g_nc2 + (orow * NO + i_blk) * 2 + oseg * 4;
    const float* pos  = g_so2 + (orow * NO + i_blk) * 2 + oseg * 4;
    const int xstep = ROWS_CH * NB * 2;      // 65536 floats per chunk
    const int ostep = ROWS_CH * NO * 2;      // 8192 floats per chunk

    auto issue = [&](int c, int p) {
        unsigned base = sb + (unsigned)(p * BUF_BYTES);
        cp16(base + (unsigned)(t * 16),                    pxc0 + c * xstep);
        cp16(base + (unsigned)((t + 128) * 16),            pxc1 + c * xstep);
        cp16(base + (unsigned)(OFF_SX * 4 + t * 16),       pxs0 + c * xstep);
        cp16(base + (unsigned)(OFF_SX * 4 + (t+128) * 16), pxs1 + c * xstep);
        cp16(base + (unsigned)(OFF_NC * 4 + t * 16),       poc  + c * ostep);
        cp16(base + (unsigned)(OFF_SO * 4 + t * 16),       pos  + c * ostep);
        asm volatile("cp.async.commit_group;\n" ::);
    };

    float a00 = 0.f, a01 = 0.f, a10 = 0.f, a11 = 0.f;

    issue(0, 0);
    issue(1, 1);

    #pragma unroll 1
    for (int c = 0; c < NCHUNK; ++c) {
        if (c < NCHUNK - 1) asm volatile("cp.async.wait_group 1;\n" ::);
        else                asm volatile("cp.async.wait_group 0;\n" ::);
        __syncthreads();

        const int p = c & 1;
        const float* buf = sbuf + p * BUF_FLOATS;
        const float* cxb = buf +          tx * 4;   // 2 b's, pair-interleaved
        const float* sxb = buf + OFF_SX + tx * 4;
        const float* ncb = buf + OFF_NC + ty * 4;   // 2 i's, pair-interleaved
        const float* sob = buf + OFF_SO + ty * 4;

        #pragma unroll
        for (int jp = 0; jp < ROWS_CH; jp += 2) {   // 4 j per iter, imm offsets
            const ulonglong2 cxA = *(const ulonglong2*)(cxb + (jp    ) * 64);
            const ulonglong2 cxB = *(const ulonglong2*)(cxb + (jp + 1) * 64);
            const ulonglong2 sxA = *(const ulonglong2*)(sxb + (jp    ) * 64);
            const ulonglong2 sxB = *(const ulonglong2*)(sxb + (jp + 1) * 64);
            const ulonglong2 nA  = *(const ulonglong2*)(ncb + (jp    ) * 32);
            const ulonglong2 nB  = *(const ulonglong2*)(ncb + (jp + 1) * 32);
            const ulonglong2 oA  = *(const ulonglong2*)(sob + (jp    ) * 32);
            const ulonglong2 oB  = *(const ulonglong2*)(sob + (jp + 1) * 32);

            // (b0, i0) / (b0, i1)
            QCELL(a00, cxA.x, sxA.x, cxB.x, sxB.x, nA.x, oA.x, nB.x, oB.x);
            QCELL(a01, cxA.x, sxA.x, cxB.x, sxB.x, nA.y, oA.y, nB.y, oB.y);
            // (b1, i0) / (b1, i1)
            QCELL(a10, cxA.y, sxA.y, cxB.y, sxB.y, nA.x, oA.x, nB.x, oB.x);
            QCELL(a11, cxA.y, sxA.y, cxB.y, sxB.y, nA.y, oA.y, nB.y, oB.y);
        }
        __syncthreads();   // all reads of buffer p done
        if (c + 2 < NCHUNK) issue(c + 2, p);
    }

    const int b0 = b_blk + tx * 2;
    const int i0 = i_blk + ty * 2;
    float2 r0, r1;
    r0.x = fmaf(negK, a00, (float)NI);
    r0.y = fmaf(negK, a01, (float)NI);
    r1.x = fmaf(negK, a10, (float)NI);
    r1.y = fmaf(negK, a11, (float)NI);
    *(float2*)(out + (b0 + 0) * NO + i0) = r0;
    *(float2*)(out + (b0 + 1) * NO + i0) = r1;
}

extern "C" void kernel_launch(void* const* d_in, const int* in_sizes, int n_in,
                              void* d_out, int out_size) {
    const float* x   = (const float*)d_in[0];   // input_matrix [2048, 256]
    const float* off = (const float*)d_in[1];   // phase_offset [256, 256]
    float* out = (float*)d_out;                 // [2048, 256]

    // Physics constants
    const double PI     = 3.14159265358979323846;
    const double RADIUS = 5e-6;
    const double KAPPA  = 0.1;
    const double N_EFF  = 3.48;
    const double LAMBDA = 1.55e-6;
    const double LOSS_A = 0.99;

    const double t   = sqrt(1.0 - KAPPA);
    const double a   = LOSS_A;
    const double rho = a * t;
    const double phi0 = fmod(2.0 * PI * N_EFF * (2.0 * PI * RADIUS) / LAMBDA, 2.0 * PI);

    const float Qc      = (float)(1.0 + rho * rho);
    const float two_rho = (float)(2.0 * rho);
    const float negK    = (float)(-(1.0 - t * t) * (1.0 - a * a));

    unsigned int qbits;
    memcpy(&qbits, &Qc, 4);
    const ull Q2 = ((ull)qbits << 32) | qbits;   // packed (Qc, Qc)

    prep_all<<<576, 256>>>(x, off, (float)phi0, two_rho);

    const int smem_bytes = 2 * BUF_BYTES;   // 24 KB
    cudaFuncSetAttribute(photonic_main,
                         cudaFuncAttributeMaxDynamicSharedMemorySize, smem_bytes);
    dim3 grid(NB / 32, NO / 16);   // (64, 16) = 1024 CTAs
    photonic_main<<<grid, 128, smem_bytes>>>(out, Q2, negK);
}